// round 4
// baseline (speedup 1.0000x reference)
#include <cuda_runtime.h>
#include <cuda_bf16.h>
#include <math_constants.h>

#define NMAX 50000
#define EMAX 1250000
#define FEAT 64
#define NCLS 10
#define NPB  4          // nodes per warp batch in layer1

#define SCAN_NB 250
#define SCAN_CH 200     // SCAN_NB * SCAN_CH = 50000 >= NMAX

__device__ int   g_deg[NMAX];          // zero at entry of every call (zero-init + re-zeroed in scan)
__device__ int   g_off[NMAX + 1];
__device__ int   g_pos[NMAX];
__device__ int   g_srcs[EMAX];
__device__ int   g_scan_state[SCAN_NB];
__device__ int   g_scan_ctr;
__device__ float g_x1[(size_t)NMAX * FEAT];
__device__ float g_y[(size_t)NMAX * 16];   // W2_l @ x1, padded 10->16
__device__ float g_z[(size_t)NMAX * NCLS]; // W2_r @ x1 + b2
__device__ int   g_is64;

// ---------------------------------------------------------------------------
// hist: per-block dtype detect, histogram of dst into g_deg (assumed zero),
// and reset of scan state/ticket for the scan kernel.
// ---------------------------------------------------------------------------
__global__ void __launch_bounds__(256) hist_kernel(const void* ei, int E, int n) {
    __shared__ int sis64;
    int tid = threadIdx.x;
    if (tid < 32) {
        const long long* p = (const long long*)ei;
        int bad = 0;
        for (int j = tid; j < 64; j += 32) {
            long long v = p[j];
            if (v < 0 || v >= (long long)n) bad = 1;
        }
        bad = __any_sync(0xffffffffu, bad);
        if (tid == 0) sis64 = bad ? 0 : 1;
    }
    __syncthreads();
    int is64 = sis64;
    int e = blockIdx.x * 256 + tid;
    if (blockIdx.x == 0 && tid == 0) { g_is64 = is64; g_scan_ctr = 0; }
    if (e < SCAN_NB) g_scan_state[e] = 0;
    if (e >= E) return;
    int d;
    if (is64) d = (int)((const long long*)ei)[E + e];
    else      d = ((const int*)ei)[E + e];
    atomicAdd(&g_deg[d], 1);
}

// ---------------------------------------------------------------------------
// single-pass decoupled-lookback exclusive scan of g_deg -> g_off/g_pos.
// Also zeroes g_deg (restoring the invariant for the next call) and writes
// the g_off[n] = E sentinel. state word: bits[30:32) flag (0 none, 1 aggregate,
// 2 prefix), bits[0:30) value (E < 2^21, fits).
// ---------------------------------------------------------------------------
__global__ void __launch_bounds__(256) scan_kernel(int n) {
    __shared__ int sh[256];
    __shared__ int sbid;
    __shared__ int sex;
    int t = threadIdx.x;
    if (t == 0) sbid = atomicAdd(&g_scan_ctr, 1);
    __syncthreads();
    int bid = sbid;
    int idx = bid * SCAN_CH + t;
    int v = (t < SCAN_CH && idx < n) ? g_deg[idx] : 0;
    sh[t] = v;
    __syncthreads();
    #pragma unroll
    for (int d = 1; d < 256; d <<= 1) {
        int u = (t >= d) ? sh[t - d] : 0;
        __syncthreads();
        sh[t] += u;
        __syncthreads();
    }
    int total = sh[255];
    if (t == 0) {
        if (bid == 0) {
            atomicExch(&g_scan_state[0], (2 << 30) | total);
            sex = 0;
        } else {
            atomicExch(&g_scan_state[bid], (1 << 30) | total);
            int ex = 0, j = bid - 1;
            while (true) {
                int st = atomicAdd(&g_scan_state[j], 0);
                int f = ((unsigned)st) >> 30;
                if (f == 0) continue;
                ex += st & 0x3FFFFFFF;
                if (f == 2) break;
                --j;
            }
            atomicExch(&g_scan_state[bid], (2 << 30) | (ex + total));
            sex = ex;
        }
    }
    __syncthreads();
    int ex = sex;
    if (t < SCAN_CH && idx < n) {
        int o = ex + sh[t] - v;
        g_off[idx] = o;
        g_pos[idx] = o;
        g_deg[idx] = 0;
    }
    if (bid == SCAN_NB - 1 && t == 0) g_off[n] = ex + total;
}

__global__ void scatter_kernel(const void* ei, int E) {
    int e = blockIdx.x * blockDim.x + threadIdx.x;
    if (e >= E) return;
    int s, d;
    if (g_is64) {
        const long long* p = (const long long*)ei;
        s = (int)p[e];
        d = (int)p[E + e];
    } else {
        const int* p = (const int*)ei;
        s = p[e];
        d = p[E + e];
    }
    int pos = atomicAdd(&g_pos[d], 1);
    g_srcs[pos] = s;
}

// ---------------------------------------------------------------------------
// Layer 1: warp per NPB nodes. float4 gather: lanes 0-15 handle edge 2p,
// lanes 16-31 handle edge 2p+1 (each lane covers 4 feature columns). Then one
// shared-weight pass transforms all NPB nodes; bias + L2-normalize + ReLU.
// ---------------------------------------------------------------------------
__global__ void __launch_bounds__(256) layer1_kernel(
    const float* __restrict__ feat,
    const float* __restrict__ Wl,
    const float* __restrict__ b,
    const float* __restrict__ Wr,
    int N)
{
    __shared__ float4 sW[FEAT * 32];        // (Wl[c][k],Wl[c+32][k],Wr[c][k],Wr[c+32][k])
    __shared__ float2 sV[8][NPB * FEAT];    // per warp: NPB nodes of (mean[k], x[k])

    int tid = threadIdx.x;
    for (int idx = tid; idx < FEAT * 32; idx += 256) {
        int k = idx >> 5, c = idx & 31;
        sW[idx] = make_float4(Wl[c * FEAT + k], Wl[(c + 32) * FEAT + k],
                              Wr[c * FEAT + k], Wr[(c + 32) * FEAT + k]);
    }
    __syncthreads();

    int lane = tid & 31, w = tid >> 5;
    int half = lane >> 4;           // 0 or 1: which edge of the pair
    int slot = lane & 15;           // which float4 of the row
    int warp_global = blockIdx.x * 8 + w;
    int nwarps = gridDim.x * 8;
    float bias0 = b[lane], bias1 = b[lane + 32];

    for (int i0 = warp_global * NPB; i0 < N; i0 += nwarps * NPB) {
        #pragma unroll
        for (int t = 0; t < NPB; ++t) {
            int i = i0 + t;
            if (i >= N) break;
            int base = g_off[i];
            int deg  = g_off[i + 1] - base;
            float4 a = make_float4(0.f, 0.f, 0.f, 0.f);
            for (int j0 = 0; j0 < deg; j0 += 32) {
                int m = deg - j0; if (m > 32) m = 32;
                int s = (lane < m) ? g_srcs[base + j0 + lane] : 0;
                int np = (m + 1) >> 1;
                #pragma unroll 8
                for (int p = 0; p < np; ++p) {
                    int idx2 = 2 * p + half;
                    int sj = __shfl_sync(0xffffffffu, s, idx2);
                    float4 v = *(const float4*)(feat + (size_t)sj * FEAT + 4 * slot);
                    if (idx2 < m) { a.x += v.x; a.y += v.y; a.z += v.z; a.w += v.w; }
                }
            }
            // combine the two half-warp edge accumulators
            a.x += __shfl_down_sync(0xffffffffu, a.x, 16);
            a.y += __shfl_down_sync(0xffffffffu, a.y, 16);
            a.z += __shfl_down_sync(0xffffffffu, a.z, 16);
            a.w += __shfl_down_sync(0xffffffffu, a.w, 16);
            if (lane < 16) {
                float inv = 1.f / fmaxf((float)deg, 1.f);
                float4 xi = *(const float4*)(feat + (size_t)i * FEAT + 4 * slot);
                sV[w][t * FEAT + 4 * slot + 0] = make_float2(a.x * inv, xi.x);
                sV[w][t * FEAT + 4 * slot + 1] = make_float2(a.y * inv, xi.y);
                sV[w][t * FEAT + 4 * slot + 2] = make_float2(a.z * inv, xi.z);
                sV[w][t * FEAT + 4 * slot + 3] = make_float2(a.w * inv, xi.w);
            }
        }
        __syncwarp();

        float o0[NPB], o1[NPB];
        #pragma unroll
        for (int t = 0; t < NPB; ++t) { o0[t] = bias0; o1[t] = bias1; }
        #pragma unroll
        for (int k = 0; k < FEAT; ++k) {
            float4 ww = sW[k * 32 + lane];
            #pragma unroll
            for (int t = 0; t < NPB; ++t) {
                float2 v = sV[w][t * FEAT + k];
                o0[t] += ww.x * v.x + ww.z * v.y;
                o1[t] += ww.y * v.x + ww.w * v.y;
            }
        }
        #pragma unroll
        for (int t = 0; t < NPB; ++t) {
            int i = i0 + t;
            if (i >= N) break;
            float ss = o0[t] * o0[t] + o1[t] * o1[t];
            #pragma unroll
            for (int d = 16; d; d >>= 1) ss += __shfl_xor_sync(0xffffffffu, ss, d);
            float innorm = 1.f / fmaxf(sqrtf(ss), 1e-12f);
            g_x1[(size_t)i * FEAT + lane]      = fmaxf(o0[t] * innorm, 0.f);
            g_x1[(size_t)i * FEAT + lane + 32] = fmaxf(o1[t] * innorm, 0.f);
        }
        __syncwarp();
    }
}

// ---------------------------------------------------------------------------
// Layer 2 transform-first: per node, y = W2_l @ x1 (10-d, padded to 16 with
// zeros) and z = W2_r @ x1 + b2. Linearity: lin_l(mean x) == mean(lin_l x).
// ---------------------------------------------------------------------------
__global__ void __launch_bounds__(256) l2t_kernel(
    const float* __restrict__ Wl,
    const float* __restrict__ b,
    const float* __restrict__ Wr,
    int N)
{
    __shared__ float sW[FEAT][32];   // c<10: Wl[c][k]; 16<=c<26: Wr[c-16][k]; else 0
    __shared__ float sx[8][FEAT];

    int tid = threadIdx.x;
    for (int idx = tid; idx < FEAT * 32; idx += 256) {
        int k = idx >> 5, c = idx & 31;
        float v = 0.f;
        if (c < NCLS)                    v = Wl[c * FEAT + k];
        else if (c >= 16 && c < 16 + NCLS) v = Wr[(c - 16) * FEAT + k];
        sW[k][c] = v;
    }
    __syncthreads();

    int lane = tid & 31, w = tid >> 5;
    int warp_global = blockIdx.x * 8 + w;
    int nwarps = gridDim.x * 8;
    float bias = (lane >= 16 && lane < 16 + NCLS) ? b[lane - 16] : 0.f;

    for (int i = warp_global; i < N; i += nwarps) {
        float2 xv = *(const float2*)(g_x1 + (size_t)i * FEAT + 2 * lane);
        sx[w][2 * lane]     = xv.x;
        sx[w][2 * lane + 1] = xv.y;
        __syncwarp();
        float o = bias;
        #pragma unroll
        for (int k = 0; k < FEAT; ++k)
            o += sW[k][lane] * sx[w][k];
        if (lane < NCLS)            g_y[(size_t)i * 16 + lane] = o;
        else if (lane < 16)         g_y[(size_t)i * 16 + lane] = 0.f;
        else if (lane < 16 + NCLS)  g_z[(size_t)i * NCLS + (lane - 16)] = o;
        __syncwarp();
    }
}

// ---------------------------------------------------------------------------
// Layer 2 gather: warp per node over 64B g_y rows (2 edges per iteration,
// lanes 0-15 / 16-31), then + z, L2-normalize, log_softmax.
// ---------------------------------------------------------------------------
__global__ void __launch_bounds__(256) l2g_kernel(float* __restrict__ out, int N) {
    int tid = threadIdx.x;
    int lane = tid & 31, w = tid >> 5;
    int half = lane >> 4;
    int slot = lane & 15;
    int warp_global = blockIdx.x * 8 + w;
    int nwarps = gridDim.x * 8;

    for (int i = warp_global; i < N; i += nwarps) {
        int base = g_off[i];
        int deg  = g_off[i + 1] - base;
        float acc = 0.f;
        for (int j0 = 0; j0 < deg; j0 += 32) {
            int m = deg - j0; if (m > 32) m = 32;
            int s = (lane < m) ? g_srcs[base + j0 + lane] : 0;
            int np = (m + 1) >> 1;
            #pragma unroll 8
            for (int p = 0; p < np; ++p) {
                int idx2 = 2 * p + half;
                int sj = __shfl_sync(0xffffffffu, s, idx2);
                float v = g_y[(size_t)sj * 16 + slot];
                if (idx2 < m) acc += v;
            }
        }
        acc += __shfl_down_sync(0xffffffffu, acc, 16);
        float inv = 1.f / fmaxf((float)deg, 1.f);
        float o = acc * inv;
        if (lane < NCLS) o += g_z[(size_t)i * NCLS + lane];

        float ss = (lane < NCLS) ? o * o : 0.f;
        #pragma unroll
        for (int d = 16; d; d >>= 1) ss += __shfl_xor_sync(0xffffffffu, ss, d);
        float innorm = 1.f / fmaxf(sqrtf(ss), 1e-12f);
        o *= innorm;
        float mx = (lane < NCLS) ? o : -CUDART_INF_F;
        #pragma unroll
        for (int d = 16; d; d >>= 1) mx = fmaxf(mx, __shfl_xor_sync(0xffffffffu, mx, d));
        float ex = (lane < NCLS) ? expf(o - mx) : 0.f;
        float es = ex;
        #pragma unroll
        for (int d = 16; d; d >>= 1) es += __shfl_xor_sync(0xffffffffu, es, d);
        float lse = logf(es);
        if (lane < NCLS)
            out[(size_t)i * NCLS + lane] = (o - mx) - lse;
    }
}

extern "C" void kernel_launch(void* const* d_in, const int* in_sizes, int n_in,
                              void* d_out, int out_size) {
    const float* feat = (const float*)d_in[0];
    const void*  ei   = d_in[1];
    const float* W1l  = (const float*)d_in[2];
    const float* b1   = (const float*)d_in[3];
    const float* W1r  = (const float*)d_in[4];
    const float* W2l  = (const float*)d_in[5];
    const float* b2   = (const float*)d_in[6];
    const float* W2r  = (const float*)d_in[7];
    float* out = (float*)d_out;

    int N = in_sizes[0] / FEAT;
    int E = in_sizes[1] / 2;

    hist_kernel<<<(E + 255) / 256, 256>>>(ei, E, N);       // 1
    scan_kernel<<<SCAN_NB, 256>>>(N);                      // 2
    scatter_kernel<<<(E + 255) / 256, 256>>>(ei, E);       // 3
    layer1_kernel<<<592, 256>>>(feat, W1l, b1, W1r, N);    // 4  <- profiled
    l2t_kernel<<<592, 256>>>(W2l, b2, W2r, N);             // 5
    l2g_kernel<<<592, 256>>>(out, N);                      // 6
}

// round 5
// speedup vs baseline: 1.5015x; 1.5015x over previous
#include <cuda_runtime.h>
#include <cuda_bf16.h>
#include <math_constants.h>

#define NMAX 50000
#define EMAX 1250000
#define FEAT 64
#define NCLS 10
#define NPB  4          // nodes per warp batch in layer1

#define SCAN_NB 250
#define SCAN_CH 200     // SCAN_NB * SCAN_CH = 50000 >= NMAX

typedef unsigned long long ull;

#define FFMA2(d, a, b) asm("fma.rn.f32x2 %0, %1, %2, %0;" : "+l"(d) : "l"(a), "l"(b))
#define FADD2(d, a)    asm("add.rn.f32x2 %0, %0, %1;"     : "+l"(d) : "l"(a))
#define PACK2(d, x, y) asm("mov.b64 %0, {%1, %2};" : "=l"(d) : "f"(x), "f"(y))
#define UNPK2(x, y, d) asm("mov.b64 {%0, %1}, %2;" : "=f"(x), "=f"(y) : "l"(d))

__device__ int   g_deg[NMAX];          // zero at entry of every call (zero-init + re-zeroed in scan)
__device__ int   g_off[NMAX + 1];
__device__ int   g_pos[NMAX];
__device__ int   g_srcs[EMAX];
__device__ int   g_scan_state[SCAN_NB];
__device__ int   g_scan_ctr;
__device__ float g_x1[(size_t)NMAX * FEAT];
__device__ float g_y[(size_t)NMAX * 16];   // W2_l @ x1, padded 10->16
__device__ float g_z[(size_t)NMAX * NCLS]; // W2_r @ x1 + b2
__device__ int   g_is64;

// ---------------------------------------------------------------------------
// hist: per-block dtype detect, histogram of dst into g_deg (assumed zero),
// and reset of scan state/ticket for the scan kernel.
// ---------------------------------------------------------------------------
__global__ void __launch_bounds__(256) hist_kernel(const void* ei, int E, int n) {
    __shared__ int sis64;
    int tid = threadIdx.x;
    if (tid < 32) {
        const long long* p = (const long long*)ei;
        int bad = 0;
        for (int j = tid; j < 64; j += 32) {
            long long v = p[j];
            if (v < 0 || v >= (long long)n) bad = 1;
        }
        bad = __any_sync(0xffffffffu, bad);
        if (tid == 0) sis64 = bad ? 0 : 1;
    }
    __syncthreads();
    int is64 = sis64;
    int e = blockIdx.x * 256 + tid;
    if (blockIdx.x == 0 && tid == 0) { g_is64 = is64; g_scan_ctr = 0; }
    if (e < SCAN_NB) g_scan_state[e] = 0;
    if (e >= E) return;
    int d;
    if (is64) d = (int)((const long long*)ei)[E + e];
    else      d = ((const int*)ei)[E + e];
    atomicAdd(&g_deg[d], 1);
}

// ---------------------------------------------------------------------------
// single-pass decoupled-lookback exclusive scan of g_deg -> g_off/g_pos.
// Also zeroes g_deg (restoring the invariant for the next call) and writes
// the g_off[n] = E sentinel.
// ---------------------------------------------------------------------------
__global__ void __launch_bounds__(256) scan_kernel(int n) {
    __shared__ int sh[256];
    __shared__ int sbid;
    __shared__ int sex;
    int t = threadIdx.x;
    if (t == 0) sbid = atomicAdd(&g_scan_ctr, 1);
    __syncthreads();
    int bid = sbid;
    int idx = bid * SCAN_CH + t;
    int v = (t < SCAN_CH && idx < n) ? g_deg[idx] : 0;
    sh[t] = v;
    __syncthreads();
    #pragma unroll
    for (int d = 1; d < 256; d <<= 1) {
        int u = (t >= d) ? sh[t - d] : 0;
        __syncthreads();
        sh[t] += u;
        __syncthreads();
    }
    int total = sh[255];
    if (t == 0) {
        if (bid == 0) {
            atomicExch(&g_scan_state[0], (2 << 30) | total);
            sex = 0;
        } else {
            atomicExch(&g_scan_state[bid], (1 << 30) | total);
            int ex = 0, j = bid - 1;
            while (true) {
                int st = atomicAdd(&g_scan_state[j], 0);
                int f = ((unsigned)st) >> 30;
                if (f == 0) continue;
                ex += st & 0x3FFFFFFF;
                if (f == 2) break;
                --j;
            }
            atomicExch(&g_scan_state[bid], (2 << 30) | (ex + total));
            sex = ex;
        }
    }
    __syncthreads();
    int ex = sex;
    if (t < SCAN_CH && idx < n) {
        int o = ex + sh[t] - v;
        g_off[idx] = o;
        g_pos[idx] = o;
        g_deg[idx] = 0;
    }
    if (bid == SCAN_NB - 1 && t == 0) g_off[n] = ex + total;
}

__global__ void scatter_kernel(const void* ei, int E) {
    int e = blockIdx.x * blockDim.x + threadIdx.x;
    if (e >= E) return;
    int s, d;
    if (g_is64) {
        const long long* p = (const long long*)ei;
        s = (int)p[e];
        d = (int)p[E + e];
    } else {
        const int* p = (const int*)ei;
        s = p[e];
        d = p[E + e];
    }
    int pos = atomicAdd(&g_pos[d], 1);
    g_srcs[pos] = s;
}

// ---------------------------------------------------------------------------
// Layer 1: warp per NPB nodes. Gather (R3 form + packed f32x2 accumulate),
// then one FFMA2-based shared-weight pass transforms all NPB nodes.
// sW[k*32+c] = (Wl[c][k], Wr[c][k], Wl[c+32][k], Wr[c+32][k])
// sV holds natural (mean, x) pairs -> direct f32x2 multiplicand.
// ---------------------------------------------------------------------------
__global__ void __launch_bounds__(256) layer1_kernel(
    const float* __restrict__ feat,
    const float* __restrict__ Wl,
    const float* __restrict__ b,
    const float* __restrict__ Wr,
    int N)
{
    __shared__ float4 sW[FEAT * 32];
    __shared__ float2 sV[8][NPB * FEAT];

    int tid = threadIdx.x;
    for (int idx = tid; idx < FEAT * 32; idx += 256) {
        int k = idx >> 5, c = idx & 31;
        sW[idx] = make_float4(Wl[c * FEAT + k], Wr[c * FEAT + k],
                              Wl[(c + 32) * FEAT + k], Wr[(c + 32) * FEAT + k]);
    }
    __syncthreads();

    int lane = tid & 31, w = tid >> 5;
    int warp_global = blockIdx.x * 8 + w;
    int nwarps = gridDim.x * 8;
    float bias0 = b[lane], bias1 = b[lane + 32];

    const ull* sWq = (const ull*)sW;            // [k*64 + 2c], pairs (Wl,Wr)
    const ull* sVq;

    for (int i0 = warp_global * NPB; i0 < N; i0 += nwarps * NPB) {
        // ---- gather phase ----
        #pragma unroll
        for (int t = 0; t < NPB; ++t) {
            int i = i0 + t;
            if (i >= N) break;
            int base = g_off[i];
            int deg  = g_off[i + 1] - base;
            ull acc; PACK2(acc, 0.f, 0.f);
            for (int j0 = 0; j0 < deg; j0 += 32) {
                int m = deg - j0; if (m > 32) m = 32;
                int s = (lane < m) ? g_srcs[base + j0 + lane] : 0;
                #pragma unroll 8
                for (int j = 0; j < m; ++j) {
                    int sj = __shfl_sync(0xffffffffu, s, j);
                    ull v = *(const ull*)(feat + (size_t)sj * FEAT + 2 * lane);
                    FADD2(acc, v);
                }
            }
            float ax, ay; UNPK2(ax, ay, acc);
            float inv = 1.f / fmaxf((float)deg, 1.f);
            float2 xi = *(const float2*)(feat + (size_t)i * FEAT + 2 * lane);
            sV[w][t * FEAT + 2 * lane]     = make_float2(ax * inv, xi.x);
            sV[w][t * FEAT + 2 * lane + 1] = make_float2(ay * inv, xi.y);
        }
        __syncwarp();

        // ---- transform phase: FFMA2, one weight pass for NPB nodes ----
        ull p0[NPB], p1[NPB];
        #pragma unroll
        for (int t = 0; t < NPB; ++t) { PACK2(p0[t], bias0, 0.f); PACK2(p1[t], bias1, 0.f); }
        sVq = (const ull*)&sV[w][0];
        #pragma unroll
        for (int k = 0; k < FEAT; ++k) {
            ull w0 = sWq[(k * 32 + lane) * 2];
            ull w1 = sWq[(k * 32 + lane) * 2 + 1];
            #pragma unroll
            for (int t = 0; t < NPB; ++t) {
                ull v = sVq[t * FEAT + k];      // (mean, x)
                FFMA2(p0[t], w0, v);            // (+Wl0*mean, +Wr0*x)
                FFMA2(p1[t], w1, v);            // (+Wl1*mean, +Wr1*x)
            }
        }
        #pragma unroll
        for (int t = 0; t < NPB; ++t) {
            int i = i0 + t;
            if (i >= N) break;
            float a, bb, o0, o1;
            UNPK2(a, bb, p0[t]); o0 = a + bb;
            UNPK2(a, bb, p1[t]); o1 = a + bb;
            float ss = o0 * o0 + o1 * o1;
            #pragma unroll
            for (int d = 16; d; d >>= 1) ss += __shfl_xor_sync(0xffffffffu, ss, d);
            float innorm = 1.f / fmaxf(sqrtf(ss), 1e-12f);
            g_x1[(size_t)i * FEAT + lane]      = fmaxf(o0 * innorm, 0.f);
            g_x1[(size_t)i * FEAT + lane + 32] = fmaxf(o1 * innorm, 0.f);
        }
        __syncwarp();
    }
}

// ---------------------------------------------------------------------------
// Layer 2 transform-first: per node, y = W2_l @ x1 (10-d, padded to 16 with
// zeros) and z = W2_r @ x1 + b2. Linearity: lin_l(mean x) == mean(lin_l x).
// ---------------------------------------------------------------------------
__global__ void __launch_bounds__(256) l2t_kernel(
    const float* __restrict__ Wl,
    const float* __restrict__ b,
    const float* __restrict__ Wr,
    int N)
{
    __shared__ float sW[FEAT][32];   // c<10: Wl[c][k]; 16<=c<26: Wr[c-16][k]; else 0
    __shared__ float sx[8][FEAT];

    int tid = threadIdx.x;
    for (int idx = tid; idx < FEAT * 32; idx += 256) {
        int k = idx >> 5, c = idx & 31;
        float v = 0.f;
        if (c < NCLS)                      v = Wl[c * FEAT + k];
        else if (c >= 16 && c < 16 + NCLS) v = Wr[(c - 16) * FEAT + k];
        sW[k][c] = v;
    }
    __syncthreads();

    int lane = tid & 31, w = tid >> 5;
    int warp_global = blockIdx.x * 8 + w;
    int nwarps = gridDim.x * 8;
    float bias = (lane >= 16 && lane < 16 + NCLS) ? b[lane - 16] : 0.f;

    for (int i = warp_global; i < N; i += nwarps) {
        float2 xv = *(const float2*)(g_x1 + (size_t)i * FEAT + 2 * lane);
        sx[w][2 * lane]     = xv.x;
        sx[w][2 * lane + 1] = xv.y;
        __syncwarp();
        float o = bias;
        #pragma unroll
        for (int k = 0; k < FEAT; ++k)
            o += sW[k][lane] * sx[w][k];
        if (lane < NCLS)            g_y[(size_t)i * 16 + lane] = o;
        else if (lane < 16)         g_y[(size_t)i * 16 + lane] = 0.f;
        else if (lane < 16 + NCLS)  g_z[(size_t)i * NCLS + (lane - 16)] = o;
        __syncwarp();
    }
}

// ---------------------------------------------------------------------------
// Layer 2 gather: warp per node over 64B g_y rows (2 edges per iteration,
// lanes 0-15 / 16-31), then + z, L2-normalize, log_softmax.
// ---------------------------------------------------------------------------
__global__ void __launch_bounds__(256) l2g_kernel(float* __restrict__ out, int N) {
    int tid = threadIdx.x;
    int lane = tid & 31, w = tid >> 5;
    int half = lane >> 4;
    int slot = lane & 15;
    int warp_global = blockIdx.x * 8 + w;
    int nwarps = gridDim.x * 8;

    for (int i = warp_global; i < N; i += nwarps) {
        int base = g_off[i];
        int deg  = g_off[i + 1] - base;
        float acc = 0.f;
        for (int j0 = 0; j0 < deg; j0 += 32) {
            int m = deg - j0; if (m > 32) m = 32;
            int s = (lane < m) ? g_srcs[base + j0 + lane] : 0;
            int np = (m + 1) >> 1;
            #pragma unroll 8
            for (int p = 0; p < np; ++p) {
                int idx2 = 2 * p + half;
                int sj = __shfl_sync(0xffffffffu, s, idx2);
                float v = g_y[(size_t)sj * 16 + slot];
                if (idx2 < m) acc += v;
            }
        }
        acc += __shfl_down_sync(0xffffffffu, acc, 16);
        float inv = 1.f / fmaxf((float)deg, 1.f);
        float o = acc * inv;
        if (lane < NCLS) o += g_z[(size_t)i * NCLS + lane];

        float ss = (lane < NCLS) ? o * o : 0.f;
        #pragma unroll
        for (int d = 16; d; d >>= 1) ss += __shfl_xor_sync(0xffffffffu, ss, d);
        float innorm = 1.f / fmaxf(sqrtf(ss), 1e-12f);
        o *= innorm;
        float mx = (lane < NCLS) ? o : -CUDART_INF_F;
        #pragma unroll
        for (int d = 16; d; d >>= 1) mx = fmaxf(mx, __shfl_xor_sync(0xffffffffu, mx, d));
        float ex = (lane < NCLS) ? expf(o - mx) : 0.f;
        float es = ex;
        #pragma unroll
        for (int d = 16; d; d >>= 1) es += __shfl_xor_sync(0xffffffffu, es, d);
        float lse = logf(es);
        if (lane < NCLS)
            out[(size_t)i * NCLS + lane] = (o - mx) - lse;
    }
}

extern "C" void kernel_launch(void* const* d_in, const int* in_sizes, int n_in,
                              void* d_out, int out_size) {
    const float* feat = (const float*)d_in[0];
    const void*  ei   = d_in[1];
    const float* W1l  = (const float*)d_in[2];
    const float* b1   = (const float*)d_in[3];
    const float* W1r  = (const float*)d_in[4];
    const float* W2l  = (const float*)d_in[5];
    const float* b2   = (const float*)d_in[6];
    const float* W2r  = (const float*)d_in[7];
    float* out = (float*)d_out;

    int N = in_sizes[0] / FEAT;
    int E = in_sizes[1] / 2;

    hist_kernel<<<(E + 255) / 256, 256>>>(ei, E, N);       // 1
    scan_kernel<<<SCAN_NB, 256>>>(N);                      // 2
    scatter_kernel<<<(E + 255) / 256, 256>>>(ei, E);       // 3
    layer1_kernel<<<592, 256>>>(feat, W1l, b1, W1r, N);    // 4  <- profiled
    l2t_kernel<<<592, 256>>>(W2l, b2, W2r, N);             // 5
    l2g_kernel<<<592, 256>>>(out, N);                      // 6
}

// round 6
// speedup vs baseline: 1.5049x; 1.0023x over previous
#include <cuda_runtime.h>
#include <cuda_bf16.h>
#include <math_constants.h>

#define NMAX 50000
#define EMAX 1250000
#define FEAT 64
#define NCLS 10
#define NPB  4          // nodes per warp batch in layer1

#define SCAN_NB 250
#define SCAN_CH 200     // SCAN_NB * SCAN_CH = 50000 >= NMAX

typedef unsigned long long ull;

#define FFMA2(d, a, b) asm("fma.rn.f32x2 %0, %1, %2, %0;" : "+l"(d) : "l"(a), "l"(b))
#define FADD2(d, a)    asm("add.rn.f32x2 %0, %0, %1;"     : "+l"(d) : "l"(a))
#define PACK2(d, x, y) asm("mov.b64 %0, {%1, %2};" : "=l"(d) : "f"(x), "f"(y))
#define UNPK2(x, y, d) asm("mov.b64 {%0, %1}, %2;" : "=f"(x), "=f"(y) : "l"(d))

__device__ int   g_deg[NMAX];          // zero at entry of every call (zero-init + re-zeroed in scan)
__device__ int   g_off[NMAX + 1];
__device__ int   g_pos[NMAX];
__device__ int   g_srcs[EMAX];
__device__ int   g_scan_state[SCAN_NB];
__device__ int   g_scan_ctr;
__device__ float g_x1[(size_t)NMAX * FEAT];
__device__ float g_y[(size_t)NMAX * 16];   // W2_l @ x1, padded 10->16
__device__ float g_z[(size_t)NMAX * NCLS]; // W2_r @ x1 + b2
__device__ int   g_is64;

// ---------------------------------------------------------------------------
// hist: per-block dtype detect, histogram of dst into g_deg (assumed zero),
// and reset of scan state/ticket for the scan kernel.
// ---------------------------------------------------------------------------
__global__ void __launch_bounds__(256) hist_kernel(const void* ei, int E, int n) {
    __shared__ int sis64;
    int tid = threadIdx.x;
    if (tid < 32) {
        const long long* p = (const long long*)ei;
        int bad = 0;
        for (int j = tid; j < 64; j += 32) {
            long long v = p[j];
            if (v < 0 || v >= (long long)n) bad = 1;
        }
        bad = __any_sync(0xffffffffu, bad);
        if (tid == 0) sis64 = bad ? 0 : 1;
    }
    __syncthreads();
    int is64 = sis64;
    int e = blockIdx.x * 256 + tid;
    if (blockIdx.x == 0 && tid == 0) { g_is64 = is64; g_scan_ctr = 0; }
    if (e < SCAN_NB) g_scan_state[e] = 0;
    if (e >= E) return;
    int d;
    if (is64) d = (int)((const long long*)ei)[E + e];
    else      d = ((const int*)ei)[E + e];
    atomicAdd(&g_deg[d], 1);
}

// ---------------------------------------------------------------------------
// single-pass decoupled-lookback exclusive scan of g_deg -> g_off/g_pos.
// Also zeroes g_deg and writes the g_off[n] = E sentinel.
// ---------------------------------------------------------------------------
__global__ void __launch_bounds__(256) scan_kernel(int n) {
    __shared__ int sh[256];
    __shared__ int sbid;
    __shared__ int sex;
    int t = threadIdx.x;
    if (t == 0) sbid = atomicAdd(&g_scan_ctr, 1);
    __syncthreads();
    int bid = sbid;
    int idx = bid * SCAN_CH + t;
    int v = (t < SCAN_CH && idx < n) ? g_deg[idx] : 0;
    sh[t] = v;
    __syncthreads();
    #pragma unroll
    for (int d = 1; d < 256; d <<= 1) {
        int u = (t >= d) ? sh[t - d] : 0;
        __syncthreads();
        sh[t] += u;
        __syncthreads();
    }
    int total = sh[255];
    if (t == 0) {
        if (bid == 0) {
            atomicExch(&g_scan_state[0], (2 << 30) | total);
            sex = 0;
        } else {
            atomicExch(&g_scan_state[bid], (1 << 30) | total);
            int ex = 0, j = bid - 1;
            while (true) {
                int st = atomicAdd(&g_scan_state[j], 0);
                int f = ((unsigned)st) >> 30;
                if (f == 0) continue;
                ex += st & 0x3FFFFFFF;
                if (f == 2) break;
                --j;
            }
            atomicExch(&g_scan_state[bid], (2 << 30) | (ex + total));
            sex = ex;
        }
    }
    __syncthreads();
    int ex = sex;
    if (t < SCAN_CH && idx < n) {
        int o = ex + sh[t] - v;
        g_off[idx] = o;
        g_pos[idx] = o;
        g_deg[idx] = 0;
    }
    if (bid == SCAN_NB - 1 && t == 0) g_off[n] = ex + total;
}

__global__ void scatter_kernel(const void* ei, int E) {
    int e = blockIdx.x * blockDim.x + threadIdx.x;
    if (e >= E) return;
    int s, d;
    if (g_is64) {
        const long long* p = (const long long*)ei;
        s = (int)p[e];
        d = (int)p[E + e];
    } else {
        const int* p = (const int*)ei;
        s = p[e];
        d = p[E + e];
    }
    int pos = atomicAdd(&g_pos[d], 1);
    g_srcs[pos] = s;
}

// ---------------------------------------------------------------------------
// Layer 1: warp per NPB nodes.
// Gather: dual-accumulator packed f32x2 neighbor sum.
// Transform: 2 k's per iteration, all LDS.128:
//   sWa[kk*32+c] = (Wl[c][k0],    Wr[c][k0],    Wl[c][k1],    Wr[c][k1])
//   sWb[kk*32+c] = (Wl[c+32][k0], Wr[c+32][k0], Wl[c+32][k1], Wr[c+32][k1])
//   sV[t][2kk..2kk+1] = (mean[k0], x[k0], mean[k1], x[k1])  (16B broadcast)
// ---------------------------------------------------------------------------
__global__ void __launch_bounds__(256) layer1_kernel(
    const float* __restrict__ feat,
    const float* __restrict__ Wl,
    const float* __restrict__ b,
    const float* __restrict__ Wr,
    int N)
{
    __shared__ float4 sWa[32 * 32];         // 16KB
    __shared__ float4 sWb[32 * 32];         // 16KB
    __shared__ float2 sV[8][NPB * FEAT];    // 16KB

    int tid = threadIdx.x;
    for (int idx = tid; idx < 32 * 32; idx += 256) {
        int kk = idx >> 5, c = idx & 31;
        int k0 = 2 * kk, k1 = 2 * kk + 1;
        sWa[idx] = make_float4(Wl[c * FEAT + k0],        Wr[c * FEAT + k0],
                               Wl[c * FEAT + k1],        Wr[c * FEAT + k1]);
        sWb[idx] = make_float4(Wl[(c + 32) * FEAT + k0], Wr[(c + 32) * FEAT + k0],
                               Wl[(c + 32) * FEAT + k1], Wr[(c + 32) * FEAT + k1]);
    }
    __syncthreads();

    int lane = tid & 31, w = tid >> 5;
    int warp_global = blockIdx.x * 8 + w;
    int nwarps = gridDim.x * 8;
    float bias0 = b[lane], bias1 = b[lane + 32];

    const ulonglong2* sWaq = (const ulonglong2*)sWa;
    const ulonglong2* sWbq = (const ulonglong2*)sWb;

    for (int i0 = warp_global * NPB; i0 < N; i0 += nwarps * NPB) {
        // ---- gather phase ----
        #pragma unroll
        for (int t = 0; t < NPB; ++t) {
            int i = i0 + t;
            if (i >= N) break;
            int base = g_off[i];
            int deg  = g_off[i + 1] - base;
            ull acc0, acc1;
            PACK2(acc0, 0.f, 0.f);
            PACK2(acc1, 0.f, 0.f);
            for (int j0 = 0; j0 < deg; j0 += 32) {
                int m = deg - j0; if (m > 32) m = 32;
                int s = (lane < m) ? g_srcs[base + j0 + lane] : 0;
                int j = 0;
                #pragma unroll 4
                for (; j + 1 < m; j += 2) {
                    int sj0 = __shfl_sync(0xffffffffu, s, j);
                    int sj1 = __shfl_sync(0xffffffffu, s, j + 1);
                    ull v0 = *(const ull*)(feat + (size_t)sj0 * FEAT + 2 * lane);
                    ull v1 = *(const ull*)(feat + (size_t)sj1 * FEAT + 2 * lane);
                    FADD2(acc0, v0);
                    FADD2(acc1, v1);
                }
                if (j < m) {
                    int sj = __shfl_sync(0xffffffffu, s, j);
                    ull v = *(const ull*)(feat + (size_t)sj * FEAT + 2 * lane);
                    FADD2(acc0, v);
                }
            }
            FADD2(acc0, acc1);
            float ax, ay; UNPK2(ax, ay, acc0);
            float inv = 1.f / fmaxf((float)deg, 1.f);
            float2 xi = *(const float2*)(feat + (size_t)i * FEAT + 2 * lane);
            *(float4*)&sV[w][t * FEAT + 2 * lane] =
                make_float4(ax * inv, xi.x, ay * inv, xi.y);
        }
        __syncwarp();

        // ---- transform phase: 2 k's per iter, FFMA2 ----
        ull p0[NPB], p1[NPB];
        #pragma unroll
        for (int t = 0; t < NPB; ++t) { PACK2(p0[t], bias0, 0.f); PACK2(p1[t], bias1, 0.f); }
        const ulonglong2* sVq = (const ulonglong2*)&sV[w][0];   // [t*32 + kk]
        #pragma unroll
        for (int kk = 0; kk < 32; ++kk) {
            ulonglong2 wa = sWaq[kk * 32 + lane];
            ulonglong2 wb = sWbq[kk * 32 + lane];
            #pragma unroll
            for (int t = 0; t < NPB; ++t) {
                ulonglong2 v = sVq[t * 32 + kk];   // broadcast 16B
                FFMA2(p0[t], wa.x, v.x);
                FFMA2(p0[t], wa.y, v.y);
                FFMA2(p1[t], wb.x, v.x);
                FFMA2(p1[t], wb.y, v.y);
            }
        }
        #pragma unroll
        for (int t = 0; t < NPB; ++t) {
            int i = i0 + t;
            if (i >= N) break;
            float a, bb, o0, o1;
            UNPK2(a, bb, p0[t]); o0 = a + bb;
            UNPK2(a, bb, p1[t]); o1 = a + bb;
            float ss = o0 * o0 + o1 * o1;
            #pragma unroll
            for (int d = 16; d; d >>= 1) ss += __shfl_xor_sync(0xffffffffu, ss, d);
            float innorm = 1.f / fmaxf(sqrtf(ss), 1e-12f);
            g_x1[(size_t)i * FEAT + lane]      = fmaxf(o0 * innorm, 0.f);
            g_x1[(size_t)i * FEAT + lane + 32] = fmaxf(o1 * innorm, 0.f);
        }
        __syncwarp();
    }
}

// ---------------------------------------------------------------------------
// Layer 2 transform-first: per node, y = W2_l @ x1 (10-d, padded to 16 with
// zeros) and z = W2_r @ x1 + b2. Linearity: lin_l(mean x) == mean(lin_l x).
// ---------------------------------------------------------------------------
__global__ void __launch_bounds__(256) l2t_kernel(
    const float* __restrict__ Wl,
    const float* __restrict__ b,
    const float* __restrict__ Wr,
    int N)
{
    __shared__ float sW[FEAT][32];   // c<10: Wl[c][k]; 16<=c<26: Wr[c-16][k]; else 0
    __shared__ float sx[8][FEAT];

    int tid = threadIdx.x;
    for (int idx = tid; idx < FEAT * 32; idx += 256) {
        int k = idx >> 5, c = idx & 31;
        float v = 0.f;
        if (c < NCLS)                      v = Wl[c * FEAT + k];
        else if (c >= 16 && c < 16 + NCLS) v = Wr[(c - 16) * FEAT + k];
        sW[k][c] = v;
    }
    __syncthreads();

    int lane = tid & 31, w = tid >> 5;
    int warp_global = blockIdx.x * 8 + w;
    int nwarps = gridDim.x * 8;
    float bias = (lane >= 16 && lane < 16 + NCLS) ? b[lane - 16] : 0.f;

    for (int i = warp_global; i < N; i += nwarps) {
        float2 xv = *(const float2*)(g_x1 + (size_t)i * FEAT + 2 * lane);
        sx[w][2 * lane]     = xv.x;
        sx[w][2 * lane + 1] = xv.y;
        __syncwarp();
        float o = bias;
        #pragma unroll
        for (int k = 0; k < FEAT; ++k)
            o += sW[k][lane] * sx[w][k];
        if (lane < NCLS)            g_y[(size_t)i * 16 + lane] = o;
        else if (lane < 16)         g_y[(size_t)i * 16 + lane] = 0.f;
        else if (lane < 16 + NCLS)  g_z[(size_t)i * NCLS + (lane - 16)] = o;
        __syncwarp();
    }
}

// ---------------------------------------------------------------------------
// Layer 2 gather: warp per node over 64B g_y rows (2 edges per iteration,
// lanes 0-15 / 16-31), then + z, L2-normalize, log_softmax.
// ---------------------------------------------------------------------------
__global__ void __launch_bounds__(256) l2g_kernel(float* __restrict__ out, int N) {
    int tid = threadIdx.x;
    int lane = tid & 31, w = tid >> 5;
    int half = lane >> 4;
    int slot = lane & 15;
    int warp_global = blockIdx.x * 8 + w;
    int nwarps = gridDim.x * 8;

    for (int i = warp_global; i < N; i += nwarps) {
        int base = g_off[i];
        int deg  = g_off[i + 1] - base;
        float acc = 0.f;
        for (int j0 = 0; j0 < deg; j0 += 32) {
            int m = deg - j0; if (m > 32) m = 32;
            int s = (lane < m) ? g_srcs[base + j0 + lane] : 0;
            int np = (m + 1) >> 1;
            #pragma unroll 8
            for (int p = 0; p < np; ++p) {
                int idx2 = 2 * p + half;
                int sj = __shfl_sync(0xffffffffu, s, idx2);
                float v = g_y[(size_t)sj * 16 + slot];
                if (idx2 < m) acc += v;
            }
        }
        acc += __shfl_down_sync(0xffffffffu, acc, 16);
        float inv = 1.f / fmaxf((float)deg, 1.f);
        float o = acc * inv;
        if (lane < NCLS) o += g_z[(size_t)i * NCLS + lane];

        float ss = (lane < NCLS) ? o * o : 0.f;
        #pragma unroll
        for (int d = 16; d; d >>= 1) ss += __shfl_xor_sync(0xffffffffu, ss, d);
        float innorm = 1.f / fmaxf(sqrtf(ss), 1e-12f);
        o *= innorm;
        float mx = (lane < NCLS) ? o : -CUDART_INF_F;
        #pragma unroll
        for (int d = 16; d; d >>= 1) mx = fmaxf(mx, __shfl_xor_sync(0xffffffffu, mx, d));
        float ex = (lane < NCLS) ? expf(o - mx) : 0.f;
        float es = ex;
        #pragma unroll
        for (int d = 16; d; d >>= 1) es += __shfl_xor_sync(0xffffffffu, es, d);
        float lse = logf(es);
        if (lane < NCLS)
            out[(size_t)i * NCLS + lane] = (o - mx) - lse;
    }
}

extern "C" void kernel_launch(void* const* d_in, const int* in_sizes, int n_in,
                              void* d_out, int out_size) {
    const float* feat = (const float*)d_in[0];
    const void*  ei   = d_in[1];
    const float* W1l  = (const float*)d_in[2];
    const float* b1   = (const float*)d_in[3];
    const float* W1r  = (const float*)d_in[4];
    const float* W2l  = (const float*)d_in[5];
    const float* b2   = (const float*)d_in[6];
    const float* W2r  = (const float*)d_in[7];
    float* out = (float*)d_out;

    int N = in_sizes[0] / FEAT;
    int E = in_sizes[1] / 2;

    hist_kernel<<<(E + 255) / 256, 256>>>(ei, E, N);       // 1
    scan_kernel<<<SCAN_NB, 256>>>(N);                      // 2
    scatter_kernel<<<(E + 255) / 256, 256>>>(ei, E);       // 3
    layer1_kernel<<<592, 256>>>(feat, W1l, b1, W1r, N);    // 4  <- profiled
    l2t_kernel<<<592, 256>>>(W2l, b2, W2r, N);             // 5
    l2g_kernel<<<592, 256>>>(out, N);                      // 6
}

// round 7
// speedup vs baseline: 1.5978x; 1.0617x over previous
#include <cuda_runtime.h>
#include <cuda_bf16.h>
#include <math_constants.h>

#define NMAX 50000
#define EMAX 1250000
#define FEAT 64
#define NCLS 10
#define NPB  8          // nodes per warp batch in l1trans

#define SCAN_NB 250
#define SCAN_CH 200     // SCAN_NB * SCAN_CH = 50000 >= NMAX

typedef unsigned long long ull;

#define FFMA2(d, a, b) asm("fma.rn.f32x2 %0, %1, %2, %0;" : "+l"(d) : "l"(a), "l"(b))
#define FADD2(d, a)    asm("add.rn.f32x2 %0, %0, %1;"     : "+l"(d) : "l"(a))
#define PACK2(d, x, y) asm("mov.b64 %0, {%1, %2};" : "=l"(d) : "f"(x), "f"(y))
#define UNPK2(x, y, d) asm("mov.b64 {%0, %1}, %2;" : "=f"(x), "=f"(y) : "l"(d))

__device__ int   g_deg[NMAX];
__device__ int   g_off[NMAX + 1];
__device__ int   g_pos[NMAX];
__device__ int   g_srcs[EMAX];
__device__ int   g_scan_state[SCAN_NB];
__device__ int   g_scan_ctr;
__device__ float g_mean[(size_t)NMAX * FEAT];
__device__ float g_x1[(size_t)NMAX * FEAT];
__device__ float g_y[(size_t)NMAX * 16];   // W2_l @ x1, padded 10->16
__device__ float g_z[(size_t)NMAX * NCLS]; // W2_r @ x1 + b2
__device__ int   g_is64;

// ---------------------------------------------------------------------------
__global__ void __launch_bounds__(256) hist_kernel(const void* ei, int E, int n) {
    __shared__ int sis64;
    int tid = threadIdx.x;
    if (tid < 32) {
        const long long* p = (const long long*)ei;
        int bad = 0;
        for (int j = tid; j < 64; j += 32) {
            long long v = p[j];
            if (v < 0 || v >= (long long)n) bad = 1;
        }
        bad = __any_sync(0xffffffffu, bad);
        if (tid == 0) sis64 = bad ? 0 : 1;
    }
    __syncthreads();
    int is64 = sis64;
    int e = blockIdx.x * 256 + tid;
    if (blockIdx.x == 0 && tid == 0) { g_is64 = is64; g_scan_ctr = 0; }
    if (e < SCAN_NB) g_scan_state[e] = 0;
    if (e >= E) return;
    int d;
    if (is64) d = (int)((const long long*)ei)[E + e];
    else      d = ((const int*)ei)[E + e];
    atomicAdd(&g_deg[d], 1);
}

// ---------------------------------------------------------------------------
// single-pass decoupled-lookback exclusive scan of g_deg -> g_off/g_pos.
// Also zeroes g_deg and writes the g_off[n] = E sentinel.
// ---------------------------------------------------------------------------
__global__ void __launch_bounds__(256) scan_kernel(int n) {
    __shared__ int sh[256];
    __shared__ int sbid;
    __shared__ int sex;
    int t = threadIdx.x;
    if (t == 0) sbid = atomicAdd(&g_scan_ctr, 1);
    __syncthreads();
    int bid = sbid;
    int idx = bid * SCAN_CH + t;
    int v = (t < SCAN_CH && idx < n) ? g_deg[idx] : 0;
    sh[t] = v;
    __syncthreads();
    #pragma unroll
    for (int d = 1; d < 256; d <<= 1) {
        int u = (t >= d) ? sh[t - d] : 0;
        __syncthreads();
        sh[t] += u;
        __syncthreads();
    }
    int total = sh[255];
    if (t == 0) {
        if (bid == 0) {
            atomicExch(&g_scan_state[0], (2 << 30) | total);
            sex = 0;
        } else {
            atomicExch(&g_scan_state[bid], (1 << 30) | total);
            int ex = 0, j = bid - 1;
            while (true) {
                int st = atomicAdd(&g_scan_state[j], 0);
                int f = ((unsigned)st) >> 30;
                if (f == 0) continue;
                ex += st & 0x3FFFFFFF;
                if (f == 2) break;
                --j;
            }
            atomicExch(&g_scan_state[bid], (2 << 30) | (ex + total));
            sex = ex;
        }
    }
    __syncthreads();
    int ex = sex;
    if (t < SCAN_CH && idx < n) {
        int o = ex + sh[t] - v;
        g_off[idx] = o;
        g_pos[idx] = o;
        g_deg[idx] = 0;
    }
    if (bid == SCAN_NB - 1 && t == 0) g_off[n] = ex + total;
}

__global__ void scatter_kernel(const void* ei, int E) {
    int e = blockIdx.x * blockDim.x + threadIdx.x;
    if (e >= E) return;
    int s, d;
    if (g_is64) {
        const long long* p = (const long long*)ei;
        s = (int)p[e];
        d = (int)p[E + e];
    } else {
        const int* p = (const int*)ei;
        s = p[e];
        d = p[E + e];
    }
    int pos = atomicAdd(&g_pos[d], 1);
    g_srcs[pos] = s;
}

// ---------------------------------------------------------------------------
// Layer 1 gather: warp per node, no smem -> 64 warps/SM. Dual packed f32x2
// accumulators. Writes mean row to g_mean.
// ---------------------------------------------------------------------------
__global__ void __launch_bounds__(256) l1gather_kernel(
    const float* __restrict__ feat, int N)
{
    int tid = threadIdx.x;
    int lane = tid & 31, w = tid >> 5;
    int wg = blockIdx.x * 8 + w;
    int nw = gridDim.x * 8;

    for (int i = wg; i < N; i += nw) {
        int base = g_off[i];
        int deg  = g_off[i + 1] - base;
        ull acc0, acc1;
        PACK2(acc0, 0.f, 0.f);
        PACK2(acc1, 0.f, 0.f);
        for (int j0 = 0; j0 < deg; j0 += 32) {
            int m = deg - j0; if (m > 32) m = 32;
            int s = (lane < m) ? g_srcs[base + j0 + lane] : 0;
            int j = 0;
            #pragma unroll 4
            for (; j + 1 < m; j += 2) {
                int sj0 = __shfl_sync(0xffffffffu, s, j);
                int sj1 = __shfl_sync(0xffffffffu, s, j + 1);
                ull v0 = *(const ull*)(feat + (size_t)sj0 * FEAT + 2 * lane);
                ull v1 = *(const ull*)(feat + (size_t)sj1 * FEAT + 2 * lane);
                FADD2(acc0, v0);
                FADD2(acc1, v1);
            }
            if (j < m) {
                int sj = __shfl_sync(0xffffffffu, s, j);
                ull v = *(const ull*)(feat + (size_t)sj * FEAT + 2 * lane);
                FADD2(acc0, v);
            }
        }
        FADD2(acc0, acc1);
        float ax, ay; UNPK2(ax, ay, acc0);
        float inv = 1.f / fmaxf((float)deg, 1.f);
        *(float2*)(g_mean + (size_t)i * FEAT + 2 * lane) =
            make_float2(ax * inv, ay * inv);
    }
}

// ---------------------------------------------------------------------------
// Layer 1 transform: NPB=8 nodes per warp per pass. Dynamic smem (64KB):
//   sWa[kk*32+c] = (Wl[c][k0],    Wr[c][k0],    Wl[c][k1],    Wr[c][k1])
//   sWb[kk*32+c] = (Wl[c+32][k0], Wr[c+32][k0], Wl[c+32][k1], Wr[c+32][k1])
//   sV[w][t*64 + 2k..2k+1] = (mean[k0], x[k0], mean[k1], x[k1])
// ---------------------------------------------------------------------------
__global__ void __launch_bounds__(256, 3) l1trans_kernel(
    const float* __restrict__ feat,
    const float* __restrict__ Wl,
    const float* __restrict__ b,
    const float* __restrict__ Wr,
    int N)
{
    extern __shared__ char dsm[];
    float4* sWa = (float4*)dsm;                 // 16KB
    float4* sWb = sWa + 32 * 32;                // 16KB
    float2* sV  = (float2*)(sWb + 32 * 32);     // 32KB: [8 warps][NPB*FEAT]

    int tid = threadIdx.x;
    for (int idx = tid; idx < 32 * 32; idx += 256) {
        int kk = idx >> 5, c = idx & 31;
        int k0 = 2 * kk, k1 = 2 * kk + 1;
        sWa[idx] = make_float4(Wl[c * FEAT + k0],        Wr[c * FEAT + k0],
                               Wl[c * FEAT + k1],        Wr[c * FEAT + k1]);
        sWb[idx] = make_float4(Wl[(c + 32) * FEAT + k0], Wr[(c + 32) * FEAT + k0],
                               Wl[(c + 32) * FEAT + k1], Wr[(c + 32) * FEAT + k1]);
    }
    __syncthreads();

    int lane = tid & 31, w = tid >> 5;
    int wg = blockIdx.x * 8 + w;
    int nw = gridDim.x * 8;
    float bias0 = b[lane], bias1 = b[lane + 32];

    const ulonglong2* sWaq = (const ulonglong2*)sWa;
    const ulonglong2* sWbq = (const ulonglong2*)sWb;
    float2* sVw = sV + w * (NPB * FEAT);
    const ulonglong2* sVq = (const ulonglong2*)sVw;   // [t*32 + kk]

    for (int i0 = wg * NPB; i0 < N; i0 += nw * NPB) {
        // stage NPB nodes of (mean, x) into shared
        #pragma unroll
        for (int t = 0; t < NPB; ++t) {
            int i = i0 + t;
            if (i >= N) break;
            float2 mv = *(const float2*)(g_mean + (size_t)i * FEAT + 2 * lane);
            float2 xv = *(const float2*)(feat   + (size_t)i * FEAT + 2 * lane);
            *(float4*)&sVw[t * FEAT + 2 * lane] = make_float4(mv.x, xv.x, mv.y, xv.y);
        }
        __syncwarp();

        ull p0[NPB], p1[NPB];
        #pragma unroll
        for (int t = 0; t < NPB; ++t) { PACK2(p0[t], bias0, 0.f); PACK2(p1[t], bias1, 0.f); }
        #pragma unroll
        for (int kk = 0; kk < 32; ++kk) {
            ulonglong2 wa = sWaq[kk * 32 + lane];
            ulonglong2 wb = sWbq[kk * 32 + lane];
            #pragma unroll
            for (int t = 0; t < NPB; ++t) {
                ulonglong2 v = sVq[t * 32 + kk];   // 16B broadcast
                FFMA2(p0[t], wa.x, v.x);
                FFMA2(p0[t], wa.y, v.y);
                FFMA2(p1[t], wb.x, v.x);
                FFMA2(p1[t], wb.y, v.y);
            }
        }
        #pragma unroll
        for (int t = 0; t < NPB; ++t) {
            int i = i0 + t;
            if (i >= N) break;
            float a, bb, o0, o1;
            UNPK2(a, bb, p0[t]); o0 = a + bb;
            UNPK2(a, bb, p1[t]); o1 = a + bb;
            float ss = o0 * o0 + o1 * o1;
            #pragma unroll
            for (int d = 16; d; d >>= 1) ss += __shfl_xor_sync(0xffffffffu, ss, d);
            float innorm = 1.f / fmaxf(sqrtf(ss), 1e-12f);
            g_x1[(size_t)i * FEAT + lane]      = fmaxf(o0 * innorm, 0.f);
            g_x1[(size_t)i * FEAT + lane + 32] = fmaxf(o1 * innorm, 0.f);
        }
        __syncwarp();
    }
}

// ---------------------------------------------------------------------------
// Layer 2 transform-first: y = W2_l @ x1 (padded 10->16), z = W2_r @ x1 + b2.
// ---------------------------------------------------------------------------
__global__ void __launch_bounds__(256) l2t_kernel(
    const float* __restrict__ Wl,
    const float* __restrict__ b,
    const float* __restrict__ Wr,
    int N)
{
    __shared__ float sW[FEAT][32];
    __shared__ float sx[8][FEAT];

    int tid = threadIdx.x;
    for (int idx = tid; idx < FEAT * 32; idx += 256) {
        int k = idx >> 5, c = idx & 31;
        float v = 0.f;
        if (c < NCLS)                      v = Wl[c * FEAT + k];
        else if (c >= 16 && c < 16 + NCLS) v = Wr[(c - 16) * FEAT + k];
        sW[k][c] = v;
    }
    __syncthreads();

    int lane = tid & 31, w = tid >> 5;
    int wg = blockIdx.x * 8 + w;
    int nw = gridDim.x * 8;
    float bias = (lane >= 16 && lane < 16 + NCLS) ? b[lane - 16] : 0.f;

    for (int i = wg; i < N; i += nw) {
        float2 xv = *(const float2*)(g_x1 + (size_t)i * FEAT + 2 * lane);
        sx[w][2 * lane]     = xv.x;
        sx[w][2 * lane + 1] = xv.y;
        __syncwarp();
        float o = bias;
        #pragma unroll
        for (int k = 0; k < FEAT; ++k)
            o += sW[k][lane] * sx[w][k];
        if (lane < NCLS)            g_y[(size_t)i * 16 + lane] = o;
        else if (lane < 16)         g_y[(size_t)i * 16 + lane] = 0.f;
        else if (lane < 16 + NCLS)  g_z[(size_t)i * NCLS + (lane - 16)] = o;
        __syncwarp();
    }
}

// ---------------------------------------------------------------------------
// Layer 2 gather over 64B g_y rows + epilogue (normalize, log_softmax).
// ---------------------------------------------------------------------------
__global__ void __launch_bounds__(256) l2g_kernel(float* __restrict__ out, int N) {
    int tid = threadIdx.x;
    int lane = tid & 31, w = tid >> 5;
    int half = lane >> 4;
    int slot = lane & 15;
    int wg = blockIdx.x * 8 + w;
    int nw = gridDim.x * 8;

    for (int i = wg; i < N; i += nw) {
        int base = g_off[i];
        int deg  = g_off[i + 1] - base;
        float acc = 0.f;
        for (int j0 = 0; j0 < deg; j0 += 32) {
            int m = deg - j0; if (m > 32) m = 32;
            int s = (lane < m) ? g_srcs[base + j0 + lane] : 0;
            int np = (m + 1) >> 1;
            #pragma unroll 8
            for (int p = 0; p < np; ++p) {
                int idx2 = 2 * p + half;
                int sj = __shfl_sync(0xffffffffu, s, idx2);
                float v = g_y[(size_t)sj * 16 + slot];
                if (idx2 < m) acc += v;
            }
        }
        acc += __shfl_down_sync(0xffffffffu, acc, 16);
        float inv = 1.f / fmaxf((float)deg, 1.f);
        float o = acc * inv;
        if (lane < NCLS) o += g_z[(size_t)i * NCLS + lane];

        float ss = (lane < NCLS) ? o * o : 0.f;
        #pragma unroll
        for (int d = 16; d; d >>= 1) ss += __shfl_xor_sync(0xffffffffu, ss, d);
        float innorm = 1.f / fmaxf(sqrtf(ss), 1e-12f);
        o *= innorm;
        float mx = (lane < NCLS) ? o : -CUDART_INF_F;
        #pragma unroll
        for (int d = 16; d; d >>= 1) mx = fmaxf(mx, __shfl_xor_sync(0xffffffffu, mx, d));
        float ex = (lane < NCLS) ? expf(o - mx) : 0.f;
        float es = ex;
        #pragma unroll
        for (int d = 16; d; d >>= 1) es += __shfl_xor_sync(0xffffffffu, es, d);
        float lse = logf(es);
        if (lane < NCLS)
            out[(size_t)i * NCLS + lane] = (o - mx) - lse;
    }
}

extern "C" void kernel_launch(void* const* d_in, const int* in_sizes, int n_in,
                              void* d_out, int out_size) {
    const float* feat = (const float*)d_in[0];
    const void*  ei   = d_in[1];
    const float* W1l  = (const float*)d_in[2];
    const float* b1   = (const float*)d_in[3];
    const float* W1r  = (const float*)d_in[4];
    const float* W2l  = (const float*)d_in[5];
    const float* b2   = (const float*)d_in[6];
    const float* W2r  = (const float*)d_in[7];
    float* out = (float*)d_out;

    int N = in_sizes[0] / FEAT;
    int E = in_sizes[1] / 2;

    static int smem_set = 0;
    const int TRANS_SMEM = 64 * 1024;
    if (!smem_set) {
        cudaFuncSetAttribute(l1trans_kernel,
                             cudaFuncAttributeMaxDynamicSharedMemorySize, TRANS_SMEM);
        smem_set = 1;
    }

    hist_kernel<<<(E + 255) / 256, 256>>>(ei, E, N);             // 1
    scan_kernel<<<SCAN_NB, 256>>>(N);                            // 2
    scatter_kernel<<<(E + 255) / 256, 256>>>(ei, E);             // 3
    l1gather_kernel<<<1184, 256>>>(feat, N);                     // 4 <- profiled
    l1trans_kernel<<<444, 256, TRANS_SMEM>>>(feat, W1l, b1, W1r, N); // 5
    l2t_kernel<<<592, 256>>>(W2l, b2, W2r, N);                   // 6
    l2g_kernel<<<592, 256>>>(out, N);                            // 7
}

// round 8
// speedup vs baseline: 1.8315x; 1.1463x over previous
#include <cuda_runtime.h>
#include <cuda_bf16.h>
#include <math_constants.h>

#define NMAX 50000
#define EMAX 1250000
#define FEAT 64
#define NCLS 10
#define NPB  8          // nodes per warp batch in l1trans

#define SCAN_NB 250
#define SCAN_CH 200     // SCAN_NB * SCAN_CH = 50000 >= NMAX

typedef unsigned long long ull;

#define FFMA2(d, a, b) asm("fma.rn.f32x2 %0, %1, %2, %0;" : "+l"(d) : "l"(a), "l"(b))
#define FADD2(d, a)    asm("add.rn.f32x2 %0, %0, %1;"     : "+l"(d) : "l"(a))
#define PACK2(d, x, y) asm("mov.b64 %0, {%1, %2};" : "=l"(d) : "f"(x), "f"(y))
#define UNPK2(x, y, d) asm("mov.b64 {%0, %1}, %2;" : "=f"(x), "=f"(y) : "l"(d))

__device__ int   g_deg[NMAX];
__device__ int   g_off[NMAX + 1];
__device__ int   g_pos[NMAX];
__device__ int   g_srcs[EMAX];
__device__ int   g_scan_state[SCAN_NB];
__device__ int   g_scan_ctr;
__device__ float g_mean[(size_t)NMAX * FEAT];
__device__ float g_y[(size_t)NMAX * 16];   // W2_l @ x1, padded 10->16
__device__ float g_z[(size_t)NMAX * NCLS]; // W2_r @ x1 + b2
__device__ int   g_is64;

// ---------------------------------------------------------------------------
__global__ void __launch_bounds__(256) hist_kernel(const void* ei, int E, int n) {
    __shared__ int sis64;
    int tid = threadIdx.x;
    if (tid < 32) {
        const long long* p = (const long long*)ei;
        int bad = 0;
        for (int j = tid; j < 64; j += 32) {
            long long v = p[j];
            if (v < 0 || v >= (long long)n) bad = 1;
        }
        bad = __any_sync(0xffffffffu, bad);
        if (tid == 0) sis64 = bad ? 0 : 1;
    }
    __syncthreads();
    int is64 = sis64;
    int e = blockIdx.x * 256 + tid;
    if (blockIdx.x == 0 && tid == 0) { g_is64 = is64; g_scan_ctr = 0; }
    if (e < SCAN_NB) g_scan_state[e] = 0;
    if (e >= E) return;
    int d;
    if (is64) d = (int)((const long long*)ei)[E + e];
    else      d = ((const int*)ei)[E + e];
    atomicAdd(&g_deg[d], 1);
}

// ---------------------------------------------------------------------------
// single-pass decoupled-lookback exclusive scan of g_deg -> g_off/g_pos.
// Also zeroes g_deg and writes the g_off[n] = E sentinel.
// ---------------------------------------------------------------------------
__global__ void __launch_bounds__(256) scan_kernel(int n) {
    __shared__ int sh[256];
    __shared__ int sbid;
    __shared__ int sex;
    int t = threadIdx.x;
    if (t == 0) sbid = atomicAdd(&g_scan_ctr, 1);
    __syncthreads();
    int bid = sbid;
    int idx = bid * SCAN_CH + t;
    int v = (t < SCAN_CH && idx < n) ? g_deg[idx] : 0;
    sh[t] = v;
    __syncthreads();
    #pragma unroll
    for (int d = 1; d < 256; d <<= 1) {
        int u = (t >= d) ? sh[t - d] : 0;
        __syncthreads();
        sh[t] += u;
        __syncthreads();
    }
    int total = sh[255];
    if (t == 0) {
        if (bid == 0) {
            atomicExch(&g_scan_state[0], (2 << 30) | total);
            sex = 0;
        } else {
            atomicExch(&g_scan_state[bid], (1 << 30) | total);
            int ex = 0, j = bid - 1;
            while (true) {
                int st = atomicAdd(&g_scan_state[j], 0);
                int f = ((unsigned)st) >> 30;
                if (f == 0) continue;
                ex += st & 0x3FFFFFFF;
                if (f == 2) break;
                --j;
            }
            atomicExch(&g_scan_state[bid], (2 << 30) | (ex + total));
            sex = ex;
        }
    }
    __syncthreads();
    int ex = sex;
    if (t < SCAN_CH && idx < n) {
        int o = ex + sh[t] - v;
        g_off[idx] = o;
        g_pos[idx] = o;
        g_deg[idx] = 0;
    }
    if (bid == SCAN_NB - 1 && t == 0) g_off[n] = ex + total;
}

__global__ void scatter_kernel(const void* ei, int E) {
    int e = blockIdx.x * blockDim.x + threadIdx.x;
    if (e >= E) return;
    int s, d;
    if (g_is64) {
        const long long* p = (const long long*)ei;
        s = (int)p[e];
        d = (int)p[E + e];
    } else {
        const int* p = (const int*)ei;
        s = p[e];
        d = p[E + e];
    }
    int pos = atomicAdd(&g_pos[d], 1);
    g_srcs[pos] = s;
}

// ---------------------------------------------------------------------------
// Layer 1 gather: warp per node, no smem -> high occupancy. Dual packed f32x2
// accumulators. Writes mean row to g_mean.
// ---------------------------------------------------------------------------
__global__ void __launch_bounds__(256) l1gather_kernel(
    const float* __restrict__ feat, int N)
{
    int tid = threadIdx.x;
    int lane = tid & 31, w = tid >> 5;
    int wg = blockIdx.x * 8 + w;
    int nw = gridDim.x * 8;

    for (int i = wg; i < N; i += nw) {
        int base = g_off[i];
        int deg  = g_off[i + 1] - base;
        ull acc0, acc1;
        PACK2(acc0, 0.f, 0.f);
        PACK2(acc1, 0.f, 0.f);
        for (int j0 = 0; j0 < deg; j0 += 32) {
            int m = deg - j0; if (m > 32) m = 32;
            int s = (lane < m) ? g_srcs[base + j0 + lane] : 0;
            int j = 0;
            #pragma unroll 4
            for (; j + 1 < m; j += 2) {
                int sj0 = __shfl_sync(0xffffffffu, s, j);
                int sj1 = __shfl_sync(0xffffffffu, s, j + 1);
                ull v0 = *(const ull*)(feat + (size_t)sj0 * FEAT + 2 * lane);
                ull v1 = *(const ull*)(feat + (size_t)sj1 * FEAT + 2 * lane);
                FADD2(acc0, v0);
                FADD2(acc1, v1);
            }
            if (j < m) {
                int sj = __shfl_sync(0xffffffffu, s, j);
                ull v = *(const ull*)(feat + (size_t)sj * FEAT + 2 * lane);
                FADD2(acc0, v);
            }
        }
        FADD2(acc0, acc1);
        float ax, ay; UNPK2(ax, ay, acc0);
        float inv = 1.f / fmaxf((float)deg, 1.f);
        *(float2*)(g_mean + (size_t)i * FEAT + 2 * lane) =
            make_float2(ax * inv, ay * inv);
    }
}

// ---------------------------------------------------------------------------
// Fused layer-1 transform + layer-2 transform. NPB=8 nodes per warp per pass.
// Pass A (layer 1): x1 = relu(normalize(Wl@mean + b + Wr@x)), kept in smem.
// Pass B (layer 2): y = W2l@x1 (lanes 0..9), z = W2r@x1 + b2 (lanes 16..25).
// Dynamic smem (72KB):
//   sWa[kk*32+c] = (Wl[c][k0],    Wr[c][k0],    Wl[c][k1],    Wr[c][k1])   16KB
//   sWb          = same for c+32                                           16KB
//   sW2[kk*32+c] = (W2?[c'][k0], W2?[c'][k1])  c<10: W2l[c]; 16<=c<26: W2r  8KB
//   sV[w][...]   : pass A staging (mean,x) pairs; reused as x1 rows in B    32KB
// ---------------------------------------------------------------------------
__global__ void __launch_bounds__(256, 3) l1trans_kernel(
    const float* __restrict__ feat,
    const float* __restrict__ Wl,
    const float* __restrict__ b,
    const float* __restrict__ Wr,
    const float* __restrict__ W2l,
    const float* __restrict__ b2,
    const float* __restrict__ W2r,
    int N)
{
    extern __shared__ char dsm[];
    float4* sWa = (float4*)dsm;                 // 16KB
    float4* sWb = sWa + 32 * 32;                // 16KB
    float2* sW2 = (float2*)(sWb + 32 * 32);     // 8KB
    float2* sV  = sW2 + 32 * 32;                // 32KB: [8 warps][NPB*FEAT]

    int tid = threadIdx.x;
    for (int idx = tid; idx < 32 * 32; idx += 256) {
        int kk = idx >> 5, c = idx & 31;
        int k0 = 2 * kk, k1 = 2 * kk + 1;
        sWa[idx] = make_float4(Wl[c * FEAT + k0],        Wr[c * FEAT + k0],
                               Wl[c * FEAT + k1],        Wr[c * FEAT + k1]);
        sWb[idx] = make_float4(Wl[(c + 32) * FEAT + k0], Wr[(c + 32) * FEAT + k0],
                               Wl[(c + 32) * FEAT + k1], Wr[(c + 32) * FEAT + k1]);
        float2 w2 = make_float2(0.f, 0.f);
        if (c < NCLS)                      w2 = make_float2(W2l[c * FEAT + k0], W2l[c * FEAT + k1]);
        else if (c >= 16 && c < 16 + NCLS) w2 = make_float2(W2r[(c - 16) * FEAT + k0], W2r[(c - 16) * FEAT + k1]);
        sW2[idx] = w2;
    }
    __syncthreads();

    int lane = tid & 31, w = tid >> 5;
    int wg = blockIdx.x * 8 + w;
    int nw = gridDim.x * 8;
    float bias0 = b[lane], bias1 = b[lane + 32];
    float bias2 = (lane >= 16 && lane < 16 + NCLS) ? b2[lane - 16] : 0.f;

    const ulonglong2* sWaq = (const ulonglong2*)sWa;
    const ulonglong2* sWbq = (const ulonglong2*)sWb;
    const ull*        sW2q = (const ull*)sW2;
    float2* sVw = sV + w * (NPB * FEAT);
    const ulonglong2* sVq = (const ulonglong2*)sVw;   // [t*32 + kk]
    float* sXw = (float*)sVw;                          // pass-B reuse: [t*64 + k]

    for (int i0 = wg * NPB; i0 < N; i0 += nw * NPB) {
        // stage NPB nodes of (mean, x) into shared
        #pragma unroll
        for (int t = 0; t < NPB; ++t) {
            int i = i0 + t;
            if (i >= N) break;
            float2 mv = *(const float2*)(g_mean + (size_t)i * FEAT + 2 * lane);
            float2 xv = *(const float2*)(feat   + (size_t)i * FEAT + 2 * lane);
            *(float4*)&sVw[t * FEAT + 2 * lane] = make_float4(mv.x, xv.x, mv.y, xv.y);
        }
        __syncwarp();

        // ---- pass A: layer-1 transform ----
        ull p0[NPB], p1[NPB];
        #pragma unroll
        for (int t = 0; t < NPB; ++t) { PACK2(p0[t], bias0, 0.f); PACK2(p1[t], bias1, 0.f); }
        #pragma unroll
        for (int kk = 0; kk < 32; ++kk) {
            ulonglong2 wa = sWaq[kk * 32 + lane];
            ulonglong2 wb = sWbq[kk * 32 + lane];
            #pragma unroll
            for (int t = 0; t < NPB; ++t) {
                ulonglong2 v = sVq[t * 32 + kk];   // 16B broadcast
                FFMA2(p0[t], wa.x, v.x);
                FFMA2(p0[t], wa.y, v.y);
                FFMA2(p1[t], wb.x, v.x);
                FFMA2(p1[t], wb.y, v.y);
            }
        }
        __syncwarp();   // pass A reads of sV done before overwrite
        #pragma unroll
        for (int t = 0; t < NPB; ++t) {
            int i = i0 + t;
            if (i >= N) break;
            float a, bb, o0, o1;
            UNPK2(a, bb, p0[t]); o0 = a + bb;
            UNPK2(a, bb, p1[t]); o1 = a + bb;
            float ss = o0 * o0 + o1 * o1;
            #pragma unroll
            for (int d = 16; d; d >>= 1) ss += __shfl_xor_sync(0xffffffffu, ss, d);
            float innorm = 1.f / fmaxf(sqrtf(ss), 1e-12f);
            sXw[t * FEAT + lane]      = fmaxf(o0 * innorm, 0.f);
            sXw[t * FEAT + lane + 32] = fmaxf(o1 * innorm, 0.f);
        }
        __syncwarp();

        // ---- pass B: layer-2 transform on x1 rows in smem ----
        ull q[NPB];
        #pragma unroll
        for (int t = 0; t < NPB; ++t) PACK2(q[t], bias2, 0.f);
        #pragma unroll
        for (int kk = 0; kk < 32; ++kk) {
            ull w2 = sW2q[kk * 32 + lane];
            #pragma unroll
            for (int t = 0; t < NPB; ++t) {
                ull v = *(const ull*)&sXw[t * FEAT + 2 * kk];   // broadcast
                FFMA2(q[t], w2, v);
            }
        }
        #pragma unroll
        for (int t = 0; t < NPB; ++t) {
            int i = i0 + t;
            if (i >= N) break;
            float a, bb; UNPK2(a, bb, q[t]);
            float o = a + bb;
            if (lane < NCLS)                   g_y[(size_t)i * 16 + lane] = o;
            else if (lane < 16)                g_y[(size_t)i * 16 + lane] = 0.f;
            else if (lane < 16 + NCLS)         g_z[(size_t)i * NCLS + (lane - 16)] = o;
        }
        __syncwarp();
    }
}

// ---------------------------------------------------------------------------
// Layer 2 gather over 64B g_y rows + epilogue (normalize, log_softmax).
// Lanes 0-15 / 16-31 handle alternating edges; dual accumulators.
// ---------------------------------------------------------------------------
__global__ void __launch_bounds__(256) l2g_kernel(float* __restrict__ out, int N) {
    int tid = threadIdx.x;
    int lane = tid & 31, w = tid >> 5;
    int half = lane >> 4;
    int slot = lane & 15;
    int wg = blockIdx.x * 8 + w;
    int nw = gridDim.x * 8;

    for (int i = wg; i < N; i += nw) {
        int base = g_off[i];
        int deg  = g_off[i + 1] - base;
        float acca = 0.f, accb = 0.f;
        for (int j0 = 0; j0 < deg; j0 += 32) {
            int m = deg - j0; if (m > 32) m = 32;
            int s = (lane < m) ? g_srcs[base + j0 + lane] : 0;
            int np = (m + 1) >> 1;
            int p = 0;
            #pragma unroll 4
            for (; p + 1 < np; p += 2) {
                int ia = 2 * p + half;
                int ib = 2 * (p + 1) + half;
                int sa = __shfl_sync(0xffffffffu, s, ia);
                int sb = __shfl_sync(0xffffffffu, s, ib);
                float va = g_y[(size_t)sa * 16 + slot];
                float vb = g_y[(size_t)sb * 16 + slot];
                if (ia < m) acca += va;
                if (ib < m) accb += vb;
            }
            if (p < np) {
                int ia = 2 * p + half;
                int sa = __shfl_sync(0xffffffffu, s, ia);
                float va = g_y[(size_t)sa * 16 + slot];
                if (ia < m) acca += va;
            }
        }
        float acc = acca + accb;
        acc += __shfl_down_sync(0xffffffffu, acc, 16);
        float inv = 1.f / fmaxf((float)deg, 1.f);
        float o = acc * inv;
        if (lane < NCLS) o += g_z[(size_t)i * NCLS + lane];

        float ss = (lane < NCLS) ? o * o : 0.f;
        #pragma unroll
        for (int d = 16; d; d >>= 1) ss += __shfl_xor_sync(0xffffffffu, ss, d);
        float innorm = 1.f / fmaxf(sqrtf(ss), 1e-12f);
        o *= innorm;
        float mx = (lane < NCLS) ? o : -CUDART_INF_F;
        #pragma unroll
        for (int d = 16; d; d >>= 1) mx = fmaxf(mx, __shfl_xor_sync(0xffffffffu, mx, d));
        float ex = (lane < NCLS) ? expf(o - mx) : 0.f;
        float es = ex;
        #pragma unroll
        for (int d = 16; d; d >>= 1) es += __shfl_xor_sync(0xffffffffu, es, d);
        float lse = logf(es);
        if (lane < NCLS)
            out[(size_t)i * NCLS + lane] = (o - mx) - lse;
    }
}

extern "C" void kernel_launch(void* const* d_in, const int* in_sizes, int n_in,
                              void* d_out, int out_size) {
    const float* feat = (const float*)d_in[0];
    const void*  ei   = d_in[1];
    const float* W1l  = (const float*)d_in[2];
    const float* b1   = (const float*)d_in[3];
    const float* W1r  = (const float*)d_in[4];
    const float* W2l  = (const float*)d_in[5];
    const float* b2   = (const float*)d_in[6];
    const float* W2r  = (const float*)d_in[7];
    float* out = (float*)d_out;

    int N = in_sizes[0] / FEAT;
    int E = in_sizes[1] / 2;

    static int smem_set = 0;
    const int TRANS_SMEM = 72 * 1024;
    if (!smem_set) {
        cudaFuncSetAttribute(l1trans_kernel,
                             cudaFuncAttributeMaxDynamicSharedMemorySize, TRANS_SMEM);
        smem_set = 1;
    }

    hist_kernel<<<(E + 255) / 256, 256>>>(ei, E, N);             // 1
    scan_kernel<<<SCAN_NB, 256>>>(N);                            // 2
    scatter_kernel<<<(E + 255) / 256, 256>>>(ei, E);             // 3
    l1gather_kernel<<<1184, 256>>>(feat, N);                     // 4 <- profiled
    l1trans_kernel<<<444, 256, TRANS_SMEM>>>(feat, W1l, b1, W1r,
                                             W2l, b2, W2r, N);   // 5
    l2g_kernel<<<1184, 256>>>(out, N);                           // 6
}